// round 14
// baseline (speedup 1.0000x reference)
#include <cuda_runtime.h>
#include <cuda_fp16.h>
#include <cstdint>
#include <cstddef>

// ================= problem constants =================
#define NB 8
#define NC 32
#define C4 128
#define H1 112
#define H2 56
#define H3 28
#define M1 (NB * H1 * H1)
#define M2 (NB * H2 * H2)
#define M3 (NB * H3 * H3)

// conv spatial tile: 8 x 16 = 128 M-rows per block
#define NT1 (NB * 14 * 7)   // 784
#define NT2 (NB * 7 * 4)    // 224
#define NT3 (NB * 4 * 2)    // 64
#define NTOT (NT1 + NT2 + NT3)   // 1072
#define CONV_GRID 304            // persistent CTAs (2 per SM)

#define NCHUNK 18           // 9 taps x 2 kc halves (BK=64)
#define HALO_BYTES 46080    // 10*18 cells * 256B
#define B_STAGE 16384
#define NPIPE 3
#define SMEM_TOTAL (HALO_BYTES + NPIPE * B_STAGE)   // 95232 -> 2 CTAs/SM

#define WCONV_BLKS ((9 * C4 * C4) / 256)   // 576
#define CASC_BLKS (NB * 28 * 2)            // 448 (b, t, jhalf)

// ================= scratch =================
__device__ __half g_a1[(size_t)M1 * C4];
__device__ __half g_a2[(size_t)M2 * C4];
__device__ __half g_a3[(size_t)M3 * C4];
__device__ __half g_y1 [(size_t)M1 * C4];
__device__ __half g_y2 [(size_t)M2 * C4];
__device__ __half g_y3 [(size_t)M3 * C4];
__device__ __half g_w[(size_t)9 * C4 * C4];    // [tap][n][ic]

// ================= helpers =================
__device__ __forceinline__ uint32_t smem_u32(const void* p) {
    uint32_t a;
    asm("{ .reg .u64 t; cvta.to.shared.u64 t, %1; cvt.u32.u64 %0, t; }" : "=r"(a) : "l"(p));
    return a;
}
__device__ __forceinline__ void ldsm_x4(uint32_t& r0, uint32_t& r1, uint32_t& r2, uint32_t& r3,
                                        uint32_t addr) {
    asm volatile("ldmatrix.sync.aligned.m8n8.x4.shared.b16 {%0,%1,%2,%3}, [%4];"
                 : "=r"(r0), "=r"(r1), "=r"(r2), "=r"(r3) : "r"(addr));
}
__device__ __forceinline__ void mma16816(float* c, const uint32_t* a, const uint32_t* b) {
    asm volatile(
        "mma.sync.aligned.m16n8k16.row.col.f32.f16.f16.f32 "
        "{%0,%1,%2,%3}, {%4,%5,%6,%7}, {%8,%9}, {%0,%1,%2,%3};"
        : "+f"(c[0]), "+f"(c[1]), "+f"(c[2]), "+f"(c[3])
        : "r"(a[0]), "r"(a[1]), "r"(a[2]), "r"(a[3]), "r"(b[0]), "r"(b[1]));
}
__device__ __forceinline__ void cp16(uint32_t saddr, const void* gptr, uint32_t srcsz) {
    size_t ga = __cvta_generic_to_global(gptr);
    asm volatile("cp.async.cg.shared.global [%0], [%1], 16, %2;"
                 :: "r"(saddr), "l"(ga), "r"(srcsz) : "memory");
}
#define CP_COMMIT() asm volatile("cp.async.commit_group;" ::: "memory")
#define CP_WAIT1()  asm volatile("cp.async.wait_group 1;" ::: "memory")

// unpack 4 consecutive half channels -> 4 floats
__device__ __forceinline__ void ld_y4(const __half* p, float& v0, float& v1, float& v2, float& v3) {
    uint2 raw = *(const uint2*)p;
    __half2 h0 = *(__half2*)&raw.x;
    __half2 h1 = *(__half2*)&raw.y;
    v0 = __low2float(h0); v1 = __high2float(h0);
    v2 = __low2float(h1); v3 = __high2float(h1);
}

// ================= fused DWT cascade (+ weight convert blocks) =================
__global__ void dwtall_k(const float* __restrict__ x, const float* __restrict__ w,
                         __half* __restrict__ wh, __half* __restrict__ a1,
                         __half* __restrict__ a2, __half* __restrict__ a3) {
    if (blockIdx.x < WCONV_BLKS) {
        int idx = blockIdx.x * 256 + threadIdx.x;
        int tap = idx / (C4 * C4);
        int rem = idx - tap * C4 * C4;
        int o = rem >> 7, ic = rem & 127;
        wh[idx] = __float2half(w[((size_t)o * C4 + ic) * 9 + tap]);
        return;
    }
    __shared__ float xrow[2][NC][113];
    __shared__ float ll1s[4][NC][57];
    __shared__ float ll2s[2][NC][29];

    int blk = blockIdx.x - WCONV_BLKS;
    int jh = blk & 1;
    int t  = (blk >> 1) % 28;
    int b  = (blk >> 1) / 28;
    const int tid = threadIdx.x;
    const int c = tid & 31;
    const float* xb = x + (size_t)b * NC * 224 * 224 + (size_t)jh * 112;

    // ---- level 1: 4 row-pairs ----
#pragma unroll 1
    for (int r = 0; r < 4; r++) {
#pragma unroll
        for (int it = 0; it < 7; it++) {
            int tt = it * 256 + tid;
            int f4 = tt % 28;
            int cc = (tt / 28) & 31;
            int rr = tt / (28 * 32);
            float4 v = *(const float4*)(xb + ((size_t)cc * 224 + (8 * t + 2 * r + rr)) * 224 + f4 * 4);
            float* d = &xrow[rr][cc][f4 * 4];
            d[0] = v.x; d[1] = v.y; d[2] = v.z; d[3] = v.w;
        }
        __syncthreads();
#pragma unroll
        for (int l = 0; l < 7; l++) {
            int jl = (tid >> 5) + l * 8;    // 0..55
            float a  = xrow[0][c][2 * jl],  bb = xrow[0][c][2 * jl + 1];
            float cc = xrow[1][c][2 * jl],  dd = xrow[1][c][2 * jl + 1];
            float ll = (a + bb + cc + dd) * 0.5f;
            float lh = (a - bb + cc - dd) * 0.5f;
            float hl = (a + bb - cc - dd) * 0.5f;
            float hh = (a - bb - cc + dd) * 0.5f;
            size_t pos = (size_t)(b * H1 + 4 * t + r) * H1 + jh * 56 + jl;
            __half2 p0 = __floats2half2_rn(ll, lh), p1 = __floats2half2_rn(hl, hh);
            uint2 v; v.x = *(uint32_t*)&p0; v.y = *(uint32_t*)&p1;
            *(uint2*)(a1 + pos * C4 + c * 4) = v;
            ll1s[r][c][jl] = ll;
        }
        __syncthreads();
    }

    // ---- level 2: 2 rows ----
#pragma unroll
    for (int l = 0; l < 7; l++) {
        int idx = (tid >> 5) + l * 8;       // 0..55
        int q = idx / 28, j2 = idx - q * 28;
        float a  = ll1s[2 * q][c][2 * j2],     bb = ll1s[2 * q][c][2 * j2 + 1];
        float cc = ll1s[2 * q + 1][c][2 * j2], dd = ll1s[2 * q + 1][c][2 * j2 + 1];
        float ll = (a + bb + cc + dd) * 0.5f;
        float lh = (a - bb + cc - dd) * 0.5f;
        float hl = (a + bb - cc - dd) * 0.5f;
        float hh = (a - bb - cc + dd) * 0.5f;
        size_t pos = (size_t)(b * H2 + 2 * t + q) * H2 + jh * 28 + j2;
        __half2 p0 = __floats2half2_rn(ll, lh), p1 = __floats2half2_rn(hl, hh);
        uint2 v; v.x = *(uint32_t*)&p0; v.y = *(uint32_t*)&p1;
        *(uint2*)(a2 + pos * C4 + c * 4) = v;
        ll2s[q][c][j2] = ll;
    }
    __syncthreads();

    // ---- level 3: 1 row (448 items) ----
#pragma unroll
    for (int l = 0; l < 2; l++) {
        int idx = tid + l * 256;
        if (idx < 448) {
            int c3 = idx & 31, j3 = idx >> 5;   // j3 0..13
            float a  = ll2s[0][c3][2 * j3], bb = ll2s[0][c3][2 * j3 + 1];
            float cc = ll2s[1][c3][2 * j3], dd = ll2s[1][c3][2 * j3 + 1];
            float ll = (a + bb + cc + dd) * 0.5f;
            float lh = (a - bb + cc - dd) * 0.5f;
            float hl = (a + bb - cc - dd) * 0.5f;
            float hh = (a - bb - cc + dd) * 0.5f;
            size_t pos = (size_t)(b * H3 + t) * H3 + jh * 14 + j3;
            __half2 p0 = __floats2half2_rn(ll, lh), p1 = __floats2half2_rn(hl, hh);
            uint2 v; v.x = *(uint32_t*)&p0; v.y = *(uint32_t*)&p1;
            *(uint2*)(a3 + pos * C4 + c3 * 4) = v;
        }
    }
}

// ================= fused IDWT cascade (bias + NCHW output), y in fp16 =================
__global__ void idwtall_k(const __half* __restrict__ y1, const __half* __restrict__ y2,
                          const __half* __restrict__ y3, float* __restrict__ out,
                          const float* __restrict__ bias) {
    __shared__ float r2s[2][NC][29];
    __shared__ float r1s[4][NC][57];
    __shared__ float outs[2][NC][113];

    int blk = blockIdx.x;
    int jh = blk & 1;
    int t  = (blk >> 1) % 28;
    int b  = (blk >> 1) / 28;
    const int tid = threadIdx.x;
    const int c = tid & 31;
    const float bv = bias[c];

    // ---- idwt3 ----
#pragma unroll
    for (int l = 0; l < 2; l++) {
        int idx = tid + l * 256;
        if (idx < 448) {
            int c3 = idx & 31, j3 = idx >> 5;
            size_t pos = (size_t)(b * H3 + t) * H3 + jh * 14 + j3;
            float ll, lh, hl, hh;
            ld_y4(y3 + pos * C4 + c3 * 4, ll, lh, hl, hh);
            float a  = (ll + lh + hl + hh) * 0.5f;
            float bb = (ll - lh + hl - hh) * 0.5f;
            float cc = (ll + lh - hl - hh) * 0.5f;
            float dd = (ll - lh - hl + hh) * 0.5f;
            r2s[0][c3][2 * j3]     = a;
            r2s[0][c3][2 * j3 + 1] = bb;
            r2s[1][c3][2 * j3]     = cc;
            r2s[1][c3][2 * j3 + 1] = dd;
        }
    }
    __syncthreads();

    // ---- idwt2 ----
#pragma unroll
    for (int l = 0; l < 7; l++) {
        int idx = (tid >> 5) + l * 8;
        int q = idx / 28, j2 = idx - q * 28;
        size_t pos = (size_t)(b * H2 + 2 * t + q) * H2 + jh * 28 + j2;
        float ll, lh, hl, hh;
        ld_y4(y2 + pos * C4 + c * 4, ll, lh, hl, hh);
        ll += r2s[q][c][j2];
        float a  = (ll + lh + hl + hh) * 0.5f;
        float bb = (ll - lh + hl - hh) * 0.5f;
        float cc = (ll + lh - hl - hh) * 0.5f;
        float dd = (ll - lh - hl + hh) * 0.5f;
        r1s[2 * q][c][2 * j2]         = a;
        r1s[2 * q][c][2 * j2 + 1]     = bb;
        r1s[2 * q + 1][c][2 * j2]     = cc;
        r1s[2 * q + 1][c][2 * j2 + 1] = dd;
    }
    __syncthreads();

    // ---- idwt1 + bias + NCHW transpose, 4 row-pairs ----
    float* ob = out + (size_t)b * NC * 224 * 224 + (size_t)jh * 112;
#pragma unroll 1
    for (int r = 0; r < 4; r++) {
#pragma unroll
        for (int l = 0; l < 7; l++) {
            int jl = (tid >> 5) + l * 8;
            size_t pos = (size_t)(b * H1 + 4 * t + r) * H1 + jh * 56 + jl;
            float ll, lh, hl, hh;
            ld_y4(y1 + pos * C4 + c * 4, ll, lh, hl, hh);
            ll += r1s[r][c][jl];
            float a  = (ll + lh + hl + hh) * 0.5f + bv;
            float bb = (ll - lh + hl - hh) * 0.5f + bv;
            float cc = (ll + lh - hl - hh) * 0.5f + bv;
            float dd = (ll - lh - hl + hh) * 0.5f + bv;
            outs[0][c][2 * jl]     = a;
            outs[0][c][2 * jl + 1] = bb;
            outs[1][c][2 * jl]     = cc;
            outs[1][c][2 * jl + 1] = dd;
        }
        __syncthreads();
#pragma unroll
        for (int it = 0; it < 7; it++) {
            int tt = it * 256 + tid;
            int f4 = tt % 28;
            int c2 = (tt / 28) & 31;
            int rr = tt / (28 * 32);
            const float* sp = &outs[rr][c2][f4 * 4];
            float4 v = make_float4(sp[0], sp[1], sp[2], sp[3]);
            *(float4*)(ob + ((size_t)c2 * 224 + (8 * t + 2 * r + rr)) * 224 + f4 * 4) = v;
        }
        __syncthreads();
    }
}

// ================= conv: persistent CTAs, halo-A + B-ring, 8 warps of 64x32 =================
__global__ __launch_bounds__(256, 2)
void conv_mma(const __half* __restrict__ a1, __half* __restrict__ y1,
              const __half* __restrict__ a2, __half* __restrict__ y2,
              const __half* __restrict__ a3, __half* __restrict__ y3,
              const __half* __restrict__ wgt) {
    extern __shared__ __align__(128) char smem[];
    const uint32_t haloB = smem_u32(smem);
    const uint32_t bBase = haloB + HALO_BYTES;

    const int tid = threadIdx.x;
    const int lane = tid & 31;
    const int wid = tid >> 5;
    const int wm = wid & 1;
    const int wn = wid >> 1;

    // tile-independent ldmatrix geometry
    const int aSeg = lane >> 4;
    const int aJ = lane & 15;
    uint32_t bRowOff[2]; int bSx[2];
#pragma unroll
    for (int bt = 0; bt < 2; bt++) {
        int rowB = wn * 32 + bt * 16 + (lane & 7) + ((lane & 16) >> 1);
        bRowOff[bt] = (uint32_t)rowB * 128;
        bSx[bt] = rowB & 7;
    }
    const int bSeg = (lane >> 3) & 1;

    auto load_b = [&](int ch, uint32_t st) {
        int tap = ch >> 1, kc = ch & 1;
        const __half* wt = wgt + ((size_t)tap * C4) * C4 + kc * 64;
#pragma unroll
        for (int it = 0; it < 4; it++) {
            int idx = it * 256 + tid;
            int n = idx >> 3, q = idx & 7;
            const char* src = (const char*)(wt + (size_t)n * C4 + q * 8);
            cp16(st + (uint32_t)n * 128 + (uint32_t)((q ^ (n & 7)) << 4), src, 16u);
        }
    };

#pragma unroll 1
    for (int bid = blockIdx.x; bid < NTOT; bid += CONV_GRID) {
        // ---- decode level / batch / tile ----
        const __half* act; __half* y; int h, b, ti, tj;
        if (bid < NT1)            { act = a1; y = y1; h = H1; b = bid / 98; int r = bid % 98; ti = r / 7;  tj = r % 7; }
        else if (bid < NT1 + NT2) { int t = bid - NT1;       act = a2; y = y2; h = H2; b = t / 28; int r = t % 28; ti = r / 4; tj = r % 4; }
        else                      { int t = bid - NT1 - NT2; act = a3; y = y3; h = H3; b = t / 8;  int r = t % 8;  ti = r / 2; tj = r % 2; }
        const int w = h;
        const int oh0 = ti * 8, ow0 = tj * 16;

        __syncthreads();   // all warps done reading smem of previous tile

        // ---- halo load ----
        {
            const size_t actB = (size_t)b * h * w * C4;
#pragma unroll
            for (int it = 0; it < 12; it++) {
                int idx = it * 256 + tid;
                if (idx < 2880) {
                    int cell = idx >> 4, q = idx & 15;
                    int hr = cell / 18, hc = cell - hr * 18;
                    int ih = oh0 + hr - 1, iw = ow0 + hc - 1;
                    bool v = ((unsigned)ih < (unsigned)h) && ((unsigned)iw < (unsigned)w);
                    const char* src = (const char*)(act + actB + ((size_t)ih * w + iw) * C4 + q * 8);
                    uint32_t dst = haloB + (uint32_t)cell * 256 +
                                   (uint32_t)((((q & 7) ^ (cell & 7)) + (q & 8)) << 4);
                    cp16(dst, src, v ? 16u : 0u);
                }
            }
        }
        load_b(0, bBase);
        CP_COMMIT();
        load_b(1, bBase + B_STAGE);
        CP_COMMIT();

        float acc[4][4][4];
#pragma unroll
        for (int i = 0; i < 4; i++)
#pragma unroll
            for (int j = 0; j < 4; j++)
#pragma unroll
                for (int q = 0; q < 4; q++) acc[i][j][q] = 0.0f;

        uint32_t stC = bBase;
        uint32_t stL = bBase + 2u * B_STAGE;
        const uint32_t stEnd = bBase + 3u * B_STAGE;

#pragma unroll 1
        for (int ch = 0; ch < NCHUNK; ch++) {
            CP_WAIT1();
            __syncthreads();
            if (ch + 2 < NCHUNK) load_b(ch + 2, stL);
            CP_COMMIT();

            const int tap = ch >> 1;
            const int kc  = ch & 1;
            const int kh = tap / 3;
            const int kw = tap - kh * 3;

            uint32_t aOff[4]; int aC7[4];
#pragma unroll
            for (int mt = 0; mt < 4; mt++) {
                int cell = (wm * 4 + mt + kh) * 18 + kw + aJ;
                aOff[mt] = haloB + (uint32_t)cell * 256;
                aC7[mt] = cell & 7;
            }

#pragma unroll
            for (int ks = 0; ks < 4; ks++) {
                uint32_t af[4][4];
                const int qa = kc * 8 + ks * 2 + aSeg;
#pragma unroll
                for (int mt = 0; mt < 4; mt++) {
                    uint32_t addr = aOff[mt] +
                        (uint32_t)((((qa & 7) ^ aC7[mt]) + (qa & 8)) << 4);
                    ldsm_x4(af[mt][0], af[mt][1], af[mt][2], af[mt][3], addr);
                }
                uint32_t bf[4][2];
#pragma unroll
                for (int bt = 0; bt < 2; bt++) {
                    uint32_t r0, r1, r2, r3;
                    ldsm_x4(r0, r1, r2, r3,
                            stC + bRowOff[bt] + (uint32_t)(((ks * 2 + bSeg) ^ bSx[bt]) << 4));
                    bf[bt * 2 + 0][0] = r0; bf[bt * 2 + 0][1] = r1;
                    bf[bt * 2 + 1][0] = r2; bf[bt * 2 + 1][1] = r3;
                }
#pragma unroll
                for (int mt = 0; mt < 4; mt++)
#pragma unroll
                    for (int nt = 0; nt < 4; nt++)
                        mma16816(acc[mt][nt], af[mt], bf[nt]);
            }

            stC += B_STAGE; if (stC >= stEnd) stC = bBase;
            stL += B_STAGE; if (stL >= stEnd) stL = bBase;
        }

        // ---- epilogue: fp16 stores ----
        const int jc = lane >> 2;
        const int nBase = wn * 32 + (lane & 3) * 2;
#pragma unroll
        for (int mt = 0; mt < 4; mt++) {
            int oh = oh0 + wm * 4 + mt;
            int ow = ow0 + jc;
            bool ohv = oh < h;
            bool v0 = ohv && (ow < w);
            bool v1 = ohv && (ow + 8 < w);
            __half* d0 = y + ((size_t)(b * h + oh) * w + ow) * C4 + nBase;
            __half* d1 = d0 + 8 * C4;
#pragma unroll
            for (int nt = 0; nt < 4; nt++) {
                if (v0) *(__half2*)(d0 + nt * 8) = __floats2half2_rn(acc[mt][nt][0], acc[mt][nt][1]);
                if (v1) *(__half2*)(d1 + nt * 8) = __floats2half2_rn(acc[mt][nt][2], acc[mt][nt][3]);
            }
        }
    }
}

// ================= launch =================
extern "C" void kernel_launch(void* const* d_in, const int* in_sizes, int n_in,
                              void* d_out, int out_size) {
    const float* x    = (const float*)d_in[0];
    const float* wgt  = (const float*)d_in[1];
    const float* bias = (const float*)d_in[2];
    float* out = (float*)d_out;

    __half *a1, *a2, *a3, *wh, *y1, *y2, *y3;
    cudaGetSymbolAddress((void**)&a1, g_a1);
    cudaGetSymbolAddress((void**)&a2, g_a2);
    cudaGetSymbolAddress((void**)&a3, g_a3);
    cudaGetSymbolAddress((void**)&wh, g_w);
    cudaGetSymbolAddress((void**)&y1, g_y1);
    cudaGetSymbolAddress((void**)&y2, g_y2);
    cudaGetSymbolAddress((void**)&y3, g_y3);

    cudaFuncSetAttribute(conv_mma, cudaFuncAttributeMaxDynamicSharedMemorySize, SMEM_TOTAL);

    // 0: full DWT cascade + weight convert
    dwtall_k<<<WCONV_BLKS + CASC_BLKS, 256>>>(x, wgt, wh, a1, a2, a3);
    // 1: all convs (persistent)
    conv_mma<<<CONV_GRID, 256, SMEM_TOTAL>>>(a1, y1, a2, y2, a3, y3, wh);
    // 2: full IDWT cascade + bias + NCHW output
    idwtall_k<<<CASC_BLKS, 256>>>(y1, y2, y3, out, bias);
}

// round 15
// speedup vs baseline: 1.0310x; 1.0310x over previous
#include <cuda_runtime.h>
#include <cuda_fp16.h>
#include <cstdint>
#include <cstddef>

// ================= problem constants =================
#define NB 8
#define NC 32
#define C4 128
#define H1 112
#define H2 56
#define H3 28
#define M1 (NB * H1 * H1)
#define M2 (NB * H2 * H2)
#define M3 (NB * H3 * H3)

// conv spatial tile: 8 x 16 = 128 M-rows per block
#define NT1 (NB * 14 * 7)   // 784
#define NT2 (NB * 7 * 4)    // 224
#define NT3 (NB * 4 * 2)    // 64

#define NCHUNK 18           // 9 taps x 2 kc halves (BK=64)
#define HALO_BYTES 46080    // 10*18 cells * 256B
#define B_STAGE 16384
#define NPIPE 3
#define SMEM_TOTAL (HALO_BYTES + NPIPE * B_STAGE)   // 95232 -> 2 CTAs/SM

#define WCONV_BLKS ((9 * C4 * C4) / 256)   // 576
#define CASC_BLKS (NB * 28 * 2)            // 448 (b, t, jhalf)

// ================= scratch =================
__device__ __half g_a1[(size_t)M1 * C4];
__device__ __half g_a2[(size_t)M2 * C4];
__device__ __half g_a3[(size_t)M3 * C4];
__device__ __half g_y1 [(size_t)M1 * C4];
__device__ __half g_y2 [(size_t)M2 * C4];
__device__ __half g_y3 [(size_t)M3 * C4];
__device__ __half g_w[(size_t)9 * C4 * C4];    // [tap][n][ic]

// ================= helpers =================
__device__ __forceinline__ uint32_t smem_u32(const void* p) {
    uint32_t a;
    asm("{ .reg .u64 t; cvta.to.shared.u64 t, %1; cvt.u32.u64 %0, t; }" : "=r"(a) : "l"(p));
    return a;
}
__device__ __forceinline__ void ldsm_x4(uint32_t& r0, uint32_t& r1, uint32_t& r2, uint32_t& r3,
                                        uint32_t addr) {
    asm volatile("ldmatrix.sync.aligned.m8n8.x4.shared.b16 {%0,%1,%2,%3}, [%4];"
                 : "=r"(r0), "=r"(r1), "=r"(r2), "=r"(r3) : "r"(addr));
}
__device__ __forceinline__ void mma16816(float* c, const uint32_t* a, const uint32_t* b) {
    asm volatile(
        "mma.sync.aligned.m16n8k16.row.col.f32.f16.f16.f32 "
        "{%0,%1,%2,%3}, {%4,%5,%6,%7}, {%8,%9}, {%0,%1,%2,%3};"
        : "+f"(c[0]), "+f"(c[1]), "+f"(c[2]), "+f"(c[3])
        : "r"(a[0]), "r"(a[1]), "r"(a[2]), "r"(a[3]), "r"(b[0]), "r"(b[1]));
}
__device__ __forceinline__ void cp16(uint32_t saddr, const void* gptr, uint32_t srcsz) {
    size_t ga = __cvta_generic_to_global(gptr);
    asm volatile("cp.async.cg.shared.global [%0], [%1], 16, %2;"
                 :: "r"(saddr), "l"(ga), "r"(srcsz) : "memory");
}
#define CP_COMMIT() asm volatile("cp.async.commit_group;" ::: "memory")
#define CP_WAIT1()  asm volatile("cp.async.wait_group 1;" ::: "memory")

// unpack 4 consecutive half channels -> 4 floats
__device__ __forceinline__ void ld_y4(const __half* p, float& v0, float& v1, float& v2, float& v3) {
    uint2 raw = *(const uint2*)p;
    __half2 h0 = *(__half2*)&raw.x;
    __half2 h1 = *(__half2*)&raw.y;
    v0 = __low2float(h0); v1 = __high2float(h0);
    v2 = __low2float(h1); v3 = __high2float(h1);
}

// ================= fused DWT cascade (+ weight convert blocks) =================
__global__ void dwtall_k(const float* __restrict__ x, const float* __restrict__ w,
                         __half* __restrict__ wh, __half* __restrict__ a1,
                         __half* __restrict__ a2, __half* __restrict__ a3) {
    if (blockIdx.x < WCONV_BLKS) {
        int idx = blockIdx.x * 256 + threadIdx.x;
        int tap = idx / (C4 * C4);
        int rem = idx - tap * C4 * C4;
        int o = rem >> 7, ic = rem & 127;
        wh[idx] = __float2half(w[((size_t)o * C4 + ic) * 9 + tap]);
        return;
    }
    __shared__ float  xrow[2][NC][113];   // 28.9 KB
    __shared__ __half ll1s[4][NC][57];    // 14.6 KB
    __shared__ __half ll2s[2][NC][29];    //  3.7 KB  -> total ~47 KB, 4 CTAs/SM

    int blk = blockIdx.x - WCONV_BLKS;
    int jh = blk & 1;
    int t  = (blk >> 1) % 28;
    int b  = (blk >> 1) / 28;
    const int tid = threadIdx.x;
    const int c = tid & 31;
    const float* xb = x + (size_t)b * NC * 224 * 224 + (size_t)jh * 112;

    // ---- level 1: 4 row-pairs ----
#pragma unroll 1
    for (int r = 0; r < 4; r++) {
#pragma unroll
        for (int it = 0; it < 7; it++) {
            int tt = it * 256 + tid;
            int f4 = tt % 28;
            int cc = (tt / 28) & 31;
            int rr = tt / (28 * 32);
            float4 v = *(const float4*)(xb + ((size_t)cc * 224 + (8 * t + 2 * r + rr)) * 224 + f4 * 4);
            float* d = &xrow[rr][cc][f4 * 4];
            d[0] = v.x; d[1] = v.y; d[2] = v.z; d[3] = v.w;
        }
        __syncthreads();
#pragma unroll
        for (int l = 0; l < 7; l++) {
            int jl = (tid >> 5) + l * 8;    // 0..55
            float a  = xrow[0][c][2 * jl],  bb = xrow[0][c][2 * jl + 1];
            float cc = xrow[1][c][2 * jl],  dd = xrow[1][c][2 * jl + 1];
            float ll = (a + bb + cc + dd) * 0.5f;
            float lh = (a - bb + cc - dd) * 0.5f;
            float hl = (a + bb - cc - dd) * 0.5f;
            float hh = (a - bb - cc + dd) * 0.5f;
            size_t pos = (size_t)(b * H1 + 4 * t + r) * H1 + jh * 56 + jl;
            __half2 p0 = __floats2half2_rn(ll, lh), p1 = __floats2half2_rn(hl, hh);
            uint2 v; v.x = *(uint32_t*)&p0; v.y = *(uint32_t*)&p1;
            *(uint2*)(a1 + pos * C4 + c * 4) = v;
            ll1s[r][c][jl] = __low2half(p0);
        }
        __syncthreads();
    }

    // ---- level 2: 2 rows ----
#pragma unroll
    for (int l = 0; l < 7; l++) {
        int idx = (tid >> 5) + l * 8;       // 0..55
        int q = idx / 28, j2 = idx - q * 28;
        float a  = __half2float(ll1s[2 * q][c][2 * j2]);
        float bb = __half2float(ll1s[2 * q][c][2 * j2 + 1]);
        float cc = __half2float(ll1s[2 * q + 1][c][2 * j2]);
        float dd = __half2float(ll1s[2 * q + 1][c][2 * j2 + 1]);
        float ll = (a + bb + cc + dd) * 0.5f;
        float lh = (a - bb + cc - dd) * 0.5f;
        float hl = (a + bb - cc - dd) * 0.5f;
        float hh = (a - bb - cc + dd) * 0.5f;
        size_t pos = (size_t)(b * H2 + 2 * t + q) * H2 + jh * 28 + j2;
        __half2 p0 = __floats2half2_rn(ll, lh), p1 = __floats2half2_rn(hl, hh);
        uint2 v; v.x = *(uint32_t*)&p0; v.y = *(uint32_t*)&p1;
        *(uint2*)(a2 + pos * C4 + c * 4) = v;
        ll2s[q][c][j2] = __low2half(p0);
    }
    __syncthreads();

    // ---- level 3: 1 row (448 items) ----
#pragma unroll
    for (int l = 0; l < 2; l++) {
        int idx = tid + l * 256;
        if (idx < 448) {
            int c3 = idx & 31, j3 = idx >> 5;   // j3 0..13
            float a  = __half2float(ll2s[0][c3][2 * j3]);
            float bb = __half2float(ll2s[0][c3][2 * j3 + 1]);
            float cc = __half2float(ll2s[1][c3][2 * j3]);
            float dd = __half2float(ll2s[1][c3][2 * j3 + 1]);
            float ll = (a + bb + cc + dd) * 0.5f;
            float lh = (a - bb + cc - dd) * 0.5f;
            float hl = (a + bb - cc - dd) * 0.5f;
            float hh = (a - bb - cc + dd) * 0.5f;
            size_t pos = (size_t)(b * H3 + t) * H3 + jh * 14 + j3;
            __half2 p0 = __floats2half2_rn(ll, lh), p1 = __floats2half2_rn(hl, hh);
            uint2 v; v.x = *(uint32_t*)&p0; v.y = *(uint32_t*)&p1;
            *(uint2*)(a3 + pos * C4 + c3 * 4) = v;
        }
    }
}

// ================= fused IDWT cascade (bias + NCHW output), y + carries fp16 =================
__global__ void idwtall_k(const __half* __restrict__ y1, const __half* __restrict__ y2,
                          const __half* __restrict__ y3, float* __restrict__ out,
                          const float* __restrict__ bias) {
    __shared__ __half r2s[2][NC][29];     //  3.7 KB
    __shared__ __half r1s[4][NC][57];     // 14.6 KB
    __shared__ float  outs[2][NC][113];   // 28.9 KB -> total ~47 KB, 4 CTAs/SM

    int blk = blockIdx.x;
    int jh = blk & 1;
    int t  = (blk >> 1) % 28;
    int b  = (blk >> 1) / 28;
    const int tid = threadIdx.x;
    const int c = tid & 31;
    const float bv = bias[c];

    // ---- idwt3 ----
#pragma unroll
    for (int l = 0; l < 2; l++) {
        int idx = tid + l * 256;
        if (idx < 448) {
            int c3 = idx & 31, j3 = idx >> 5;
            size_t pos = (size_t)(b * H3 + t) * H3 + jh * 14 + j3;
            float ll, lh, hl, hh;
            ld_y4(y3 + pos * C4 + c3 * 4, ll, lh, hl, hh);
            float a  = (ll + lh + hl + hh) * 0.5f;
            float bb = (ll - lh + hl - hh) * 0.5f;
            float cc = (ll + lh - hl - hh) * 0.5f;
            float dd = (ll - lh - hl + hh) * 0.5f;
            r2s[0][c3][2 * j3]     = __float2half(a);
            r2s[0][c3][2 * j3 + 1] = __float2half(bb);
            r2s[1][c3][2 * j3]     = __float2half(cc);
            r2s[1][c3][2 * j3 + 1] = __float2half(dd);
        }
    }
    __syncthreads();

    // ---- idwt2 ----
#pragma unroll
    for (int l = 0; l < 7; l++) {
        int idx = (tid >> 5) + l * 8;
        int q = idx / 28, j2 = idx - q * 28;
        size_t pos = (size_t)(b * H2 + 2 * t + q) * H2 + jh * 28 + j2;
        float ll, lh, hl, hh;
        ld_y4(y2 + pos * C4 + c * 4, ll, lh, hl, hh);
        ll += __half2float(r2s[q][c][j2]);
        float a  = (ll + lh + hl + hh) * 0.5f;
        float bb = (ll - lh + hl - hh) * 0.5f;
        float cc = (ll + lh - hl - hh) * 0.5f;
        float dd = (ll - lh - hl + hh) * 0.5f;
        r1s[2 * q][c][2 * j2]         = __float2half(a);
        r1s[2 * q][c][2 * j2 + 1]     = __float2half(bb);
        r1s[2 * q + 1][c][2 * j2]     = __float2half(cc);
        r1s[2 * q + 1][c][2 * j2 + 1] = __float2half(dd);
    }
    __syncthreads();

    // ---- idwt1 + bias + NCHW transpose, 4 row-pairs ----
    float* ob = out + (size_t)b * NC * 224 * 224 + (size_t)jh * 112;
#pragma unroll 1
    for (int r = 0; r < 4; r++) {
#pragma unroll
        for (int l = 0; l < 7; l++) {
            int jl = (tid >> 5) + l * 8;
            size_t pos = (size_t)(b * H1 + 4 * t + r) * H1 + jh * 56 + jl;
            float ll, lh, hl, hh;
            ld_y4(y1 + pos * C4 + c * 4, ll, lh, hl, hh);
            ll += __half2float(r1s[r][c][jl]);
            float a  = (ll + lh + hl + hh) * 0.5f + bv;
            float bb = (ll - lh + hl - hh) * 0.5f + bv;
            float cc = (ll + lh - hl - hh) * 0.5f + bv;
            float dd = (ll - lh - hl + hh) * 0.5f + bv;
            outs[0][c][2 * jl]     = a;
            outs[0][c][2 * jl + 1] = bb;
            outs[1][c][2 * jl]     = cc;
            outs[1][c][2 * jl + 1] = dd;
        }
        __syncthreads();
#pragma unroll
        for (int it = 0; it < 7; it++) {
            int tt = it * 256 + tid;
            int f4 = tt % 28;
            int c2 = (tt / 28) & 31;
            int rr = tt / (28 * 32);
            const float* sp = &outs[rr][c2][f4 * 4];
            float4 v = make_float4(sp[0], sp[1], sp[2], sp[3]);
            *(float4*)(ob + ((size_t)c2 * 224 + (8 * t + 2 * r + rr)) * 224 + f4 * 4) = v;
        }
        __syncthreads();
    }
}

// ================= conv: halo-A + B-ring, 256 threads, 8 warps of 64x32; y fp16 =================
__global__ __launch_bounds__(256, 2)
void conv_mma(const __half* __restrict__ a1, __half* __restrict__ y1,
              const __half* __restrict__ a2, __half* __restrict__ y2,
              const __half* __restrict__ a3, __half* __restrict__ y3,
              const __half* __restrict__ wgt) {
    extern __shared__ __align__(128) char smem[];
    const uint32_t haloB = smem_u32(smem);
    const uint32_t bBase = haloB + HALO_BYTES;

    int bid = blockIdx.x;
    const __half* act; __half* y; int h, b, ti, tj;
    if (bid < NT1)            { act = a1; y = y1; h = H1; b = bid / 98; int r = bid % 98; ti = r / 7;  tj = r % 7; }
    else if (bid < NT1 + NT2) { int t = bid - NT1;       act = a2; y = y2; h = H2; b = t / 28; int r = t % 28; ti = r / 4; tj = r % 4; }
    else                      { int t = bid - NT1 - NT2; act = a3; y = y3; h = H3; b = t / 8;  int r = t % 8;  ti = r / 2; tj = r % 2; }
    const int w = h;
    const int oh0 = ti * 8, ow0 = tj * 16;

    const int tid = threadIdx.x;
    const int lane = tid & 31;
    const int wid = tid >> 5;
    const int wm = wid & 1;
    const int wn = wid >> 1;

    // ---- halo load ----
    {
        const size_t actB = (size_t)b * h * w * C4;
#pragma unroll
        for (int it = 0; it < 12; it++) {
            int idx = it * 256 + tid;
            if (idx < 2880) {
                int cell = idx >> 4, q = idx & 15;
                int hr = cell / 18, hc = cell - hr * 18;
                int ih = oh0 + hr - 1, iw = ow0 + hc - 1;
                bool v = ((unsigned)ih < (unsigned)h) && ((unsigned)iw < (unsigned)w);
                const char* src = (const char*)(act + actB + ((size_t)ih * w + iw) * C4 + q * 8);
                uint32_t dst = haloB + (uint32_t)cell * 256 +
                               (uint32_t)((((q & 7) ^ (cell & 7)) + (q & 8)) << 4);
                cp16(dst, src, v ? 16u : 0u);
            }
        }
    }

    auto load_b = [&](int ch, uint32_t st) {
        int tap = ch >> 1, kc = ch & 1;
        const __half* wt = wgt + ((size_t)tap * C4) * C4 + kc * 64;
#pragma unroll
        for (int it = 0; it < 4; it++) {
            int idx = it * 256 + tid;
            int n = idx >> 3, q = idx & 7;
            const char* src = (const char*)(wt + (size_t)n * C4 + q * 8);
            cp16(st + (uint32_t)n * 128 + (uint32_t)((q ^ (n & 7)) << 4), src, 16u);
        }
    };

    const int aSeg = lane >> 4;
    const int aJ = lane & 15;
    uint32_t bRowOff[2]; int bSx[2];
#pragma unroll
    for (int bt = 0; bt < 2; bt++) {
        int rowB = wn * 32 + bt * 16 + (lane & 7) + ((lane & 16) >> 1);
        bRowOff[bt] = (uint32_t)rowB * 128;
        bSx[bt] = rowB & 7;
    }
    const int bSeg = (lane >> 3) & 1;

    float acc[4][4][4];
#pragma unroll
    for (int i = 0; i < 4; i++)
#pragma unroll
        for (int j = 0; j < 4; j++)
#pragma unroll
            for (int q = 0; q < 4; q++) acc[i][j][q] = 0.0f;

    load_b(0, bBase);
    CP_COMMIT();
    load_b(1, bBase + B_STAGE);
    CP_COMMIT();

    uint32_t stC = bBase;
    uint32_t stL = bBase + 2u * B_STAGE;
    const uint32_t stEnd = bBase + 3u * B_STAGE;

#pragma unroll 1
    for (int ch = 0; ch < NCHUNK; ch++) {
        CP_WAIT1();
        __syncthreads();
        if (ch + 2 < NCHUNK) load_b(ch + 2, stL);
        CP_COMMIT();

        const int tap = ch >> 1;
        const int kc  = ch & 1;
        const int kh = tap / 3;
        const int kw = tap - kh * 3;

        uint32_t aOff[4]; int aC7[4];
#pragma unroll
        for (int mt = 0; mt < 4; mt++) {
            int cell = (wm * 4 + mt + kh) * 18 + kw + aJ;
            aOff[mt] = haloB + (uint32_t)cell * 256;
            aC7[mt] = cell & 7;
        }

#pragma unroll
        for (int ks = 0; ks < 4; ks++) {
            uint32_t af[4][4];
            const int qa = kc * 8 + ks * 2 + aSeg;
#pragma unroll
            for (int mt = 0; mt < 4; mt++) {
                uint32_t addr = aOff[mt] +
                    (uint32_t)((((qa & 7) ^ aC7[mt]) + (qa & 8)) << 4);
                ldsm_x4(af[mt][0], af[mt][1], af[mt][2], af[mt][3], addr);
            }
            uint32_t bf[4][2];
#pragma unroll
            for (int bt = 0; bt < 2; bt++) {
                uint32_t r0, r1, r2, r3;
                ldsm_x4(r0, r1, r2, r3,
                        stC + bRowOff[bt] + (uint32_t)(((ks * 2 + bSeg) ^ bSx[bt]) << 4));
                bf[bt * 2 + 0][0] = r0; bf[bt * 2 + 0][1] = r1;
                bf[bt * 2 + 1][0] = r2; bf[bt * 2 + 1][1] = r3;
            }
#pragma unroll
            for (int mt = 0; mt < 4; mt++)
#pragma unroll
                for (int nt = 0; nt < 4; nt++)
                    mma16816(acc[mt][nt], af[mt], bf[nt]);
        }

        stC += B_STAGE; if (stC >= stEnd) stC = bBase;
        stL += B_STAGE; if (stL >= stEnd) stL = bBase;
    }

    // ---- epilogue: fp16 stores ----
    const int jc = lane >> 2;
    const int nBase = wn * 32 + (lane & 3) * 2;
#pragma unroll
    for (int mt = 0; mt < 4; mt++) {
        int oh = oh0 + wm * 4 + mt;
        int ow = ow0 + jc;
        bool ohv = oh < h;
        bool v0 = ohv && (ow < w);
        bool v1 = ohv && (ow + 8 < w);
        __half* d0 = y + ((size_t)(b * h + oh) * w + ow) * C4 + nBase;
        __half* d1 = d0 + 8 * C4;
#pragma unroll
        for (int nt = 0; nt < 4; nt++) {
            if (v0) *(__half2*)(d0 + nt * 8) = __floats2half2_rn(acc[mt][nt][0], acc[mt][nt][1]);
            if (v1) *(__half2*)(d1 + nt * 8) = __floats2half2_rn(acc[mt][nt][2], acc[mt][nt][3]);
        }
    }
}

// ================= launch =================
extern "C" void kernel_launch(void* const* d_in, const int* in_sizes, int n_in,
                              void* d_out, int out_size) {
    const float* x    = (const float*)d_in[0];
    const float* wgt  = (const float*)d_in[1];
    const float* bias = (const float*)d_in[2];
    float* out = (float*)d_out;

    __half *a1, *a2, *a3, *wh, *y1, *y2, *y3;
    cudaGetSymbolAddress((void**)&a1, g_a1);
    cudaGetSymbolAddress((void**)&a2, g_a2);
    cudaGetSymbolAddress((void**)&a3, g_a3);
    cudaGetSymbolAddress((void**)&wh, g_w);
    cudaGetSymbolAddress((void**)&y1, g_y1);
    cudaGetSymbolAddress((void**)&y2, g_y2);
    cudaGetSymbolAddress((void**)&y3, g_y3);

    cudaFuncSetAttribute(conv_mma, cudaFuncAttributeMaxDynamicSharedMemorySize, SMEM_TOTAL);

    // 0: full DWT cascade + weight convert
    dwtall_k<<<WCONV_BLKS + CASC_BLKS, 256>>>(x, wgt, wh, a1, a2, a3);
    // 1: all convs
    conv_mma<<<NT1 + NT2 + NT3, 256, SMEM_TOTAL>>>(a1, y1, a2, y2, a3, y3, wh);
    // 2: full IDWT cascade + bias + NCHW output
    idwtall_k<<<CASC_BLKS, 256>>>(y1, y2, y3, out, bias);
}

// round 16
// speedup vs baseline: 1.0850x; 1.0524x over previous
#include <cuda_runtime.h>
#include <cuda_fp16.h>
#include <cstdint>
#include <cstddef>

// ================= problem constants =================
#define NB 8
#define NC 32
#define C4 128
#define H1 112
#define H2 56
#define H3 28
#define M1 (NB * H1 * H1)
#define M2 (NB * H2 * H2)
#define M3 (NB * H3 * H3)

// conv spatial tile: 8 x 16 = 128 M-rows per block
#define NT1 (NB * 14 * 7)   // 784
#define NT2 (NB * 7 * 4)    // 224
#define NT3 (NB * 4 * 2)    // 64

#define NCHUNK 9            // 9 taps, BK=128 (full ic)
#define HALO_BYTES 46080    // 10*18 cells * 256B
#define B_STAGE 32768       // 128 n-rows x 256B
#define SMEM_TOTAL (HALO_BYTES + 2 * B_STAGE)   // 111616 -> 2 CTAs/SM

#define WCONV_BLKS ((9 * C4 * C4) / 256)   // 576
#define CASC_BLKS (NB * 28 * 2)            // 448 (b, t, jhalf)

// ================= scratch =================
__device__ __half g_a1[(size_t)M1 * C4];
__device__ __half g_a2[(size_t)M2 * C4];
__device__ __half g_a3[(size_t)M3 * C4];
__device__ __half g_y1 [(size_t)M1 * C4];
__device__ __half g_y2 [(size_t)M2 * C4];
__device__ __half g_y3 [(size_t)M3 * C4];
__device__ __half g_w[(size_t)9 * C4 * C4];    // [tap][n][ic]

// ================= helpers =================
__device__ __forceinline__ uint32_t smem_u32(const void* p) {
    uint32_t a;
    asm("{ .reg .u64 t; cvta.to.shared.u64 t, %1; cvt.u32.u64 %0, t; }" : "=r"(a) : "l"(p));
    return a;
}
__device__ __forceinline__ void ldsm_x4(uint32_t& r0, uint32_t& r1, uint32_t& r2, uint32_t& r3,
                                        uint32_t addr) {
    asm volatile("ldmatrix.sync.aligned.m8n8.x4.shared.b16 {%0,%1,%2,%3}, [%4];"
                 : "=r"(r0), "=r"(r1), "=r"(r2), "=r"(r3) : "r"(addr));
}
__device__ __forceinline__ void mma16816(float* c, const uint32_t* a, const uint32_t* b) {
    asm volatile(
        "mma.sync.aligned.m16n8k16.row.col.f32.f16.f16.f32 "
        "{%0,%1,%2,%3}, {%4,%5,%6,%7}, {%8,%9}, {%0,%1,%2,%3};"
        : "+f"(c[0]), "+f"(c[1]), "+f"(c[2]), "+f"(c[3])
        : "r"(a[0]), "r"(a[1]), "r"(a[2]), "r"(a[3]), "r"(b[0]), "r"(b[1]));
}
__device__ __forceinline__ void cp16(uint32_t saddr, const void* gptr, uint32_t srcsz) {
    size_t ga = __cvta_generic_to_global(gptr);
    asm volatile("cp.async.cg.shared.global [%0], [%1], 16, %2;"
                 :: "r"(saddr), "l"(ga), "r"(srcsz) : "memory");
}
#define CP_COMMIT()  asm volatile("cp.async.commit_group;" ::: "memory")
#define CP_WAIT0()   asm volatile("cp.async.wait_group 0;" ::: "memory")

// unpack 4 consecutive half channels -> 4 floats
__device__ __forceinline__ void ld_y4(const __half* p, float& v0, float& v1, float& v2, float& v3) {
    uint2 raw = *(const uint2*)p;
    __half2 h0 = *(__half2*)&raw.x;
    __half2 h1 = *(__half2*)&raw.y;
    v0 = __low2float(h0); v1 = __high2float(h0);
    v2 = __low2float(h1); v3 = __high2float(h1);
}

// ================= fused DWT cascade (+ weight convert blocks) — R13 version =================
__global__ void dwtall_k(const float* __restrict__ x, const float* __restrict__ w,
                         __half* __restrict__ wh, __half* __restrict__ a1,
                         __half* __restrict__ a2, __half* __restrict__ a3) {
    if (blockIdx.x < WCONV_BLKS) {
        int idx = blockIdx.x * 256 + threadIdx.x;
        int tap = idx / (C4 * C4);
        int rem = idx - tap * C4 * C4;
        int o = rem >> 7, ic = rem & 127;
        wh[idx] = __float2half(w[((size_t)o * C4 + ic) * 9 + tap]);
        return;
    }
    __shared__ float xrow[2][NC][113];
    __shared__ float ll1s[4][NC][57];
    __shared__ float ll2s[2][NC][29];

    int blk = blockIdx.x - WCONV_BLKS;
    int jh = blk & 1;
    int t  = (blk >> 1) % 28;
    int b  = (blk >> 1) / 28;
    const int tid = threadIdx.x;
    const int c = tid & 31;
    const float* xb = x + (size_t)b * NC * 224 * 224 + (size_t)jh * 112;

#pragma unroll 1
    for (int r = 0; r < 4; r++) {
#pragma unroll
        for (int it = 0; it < 7; it++) {
            int tt = it * 256 + tid;
            int f4 = tt % 28;
            int cc = (tt / 28) & 31;
            int rr = tt / (28 * 32);
            float4 v = *(const float4*)(xb + ((size_t)cc * 224 + (8 * t + 2 * r + rr)) * 224 + f4 * 4);
            float* d = &xrow[rr][cc][f4 * 4];
            d[0] = v.x; d[1] = v.y; d[2] = v.z; d[3] = v.w;
        }
        __syncthreads();
#pragma unroll
        for (int l = 0; l < 7; l++) {
            int jl = (tid >> 5) + l * 8;    // 0..55
            float a  = xrow[0][c][2 * jl],  bb = xrow[0][c][2 * jl + 1];
            float cc = xrow[1][c][2 * jl],  dd = xrow[1][c][2 * jl + 1];
            float ll = (a + bb + cc + dd) * 0.5f;
            float lh = (a - bb + cc - dd) * 0.5f;
            float hl = (a + bb - cc - dd) * 0.5f;
            float hh = (a - bb - cc + dd) * 0.5f;
            size_t pos = (size_t)(b * H1 + 4 * t + r) * H1 + jh * 56 + jl;
            __half2 p0 = __floats2half2_rn(ll, lh), p1 = __floats2half2_rn(hl, hh);
            uint2 v; v.x = *(uint32_t*)&p0; v.y = *(uint32_t*)&p1;
            *(uint2*)(a1 + pos * C4 + c * 4) = v;
            ll1s[r][c][jl] = ll;
        }
        __syncthreads();
    }

#pragma unroll
    for (int l = 0; l < 7; l++) {
        int idx = (tid >> 5) + l * 8;       // 0..55
        int q = idx / 28, j2 = idx - q * 28;
        float a  = ll1s[2 * q][c][2 * j2],     bb = ll1s[2 * q][c][2 * j2 + 1];
        float cc = ll1s[2 * q + 1][c][2 * j2], dd = ll1s[2 * q + 1][c][2 * j2 + 1];
        float ll = (a + bb + cc + dd) * 0.5f;
        float lh = (a - bb + cc - dd) * 0.5f;
        float hl = (a + bb - cc - dd) * 0.5f;
        float hh = (a - bb - cc + dd) * 0.5f;
        size_t pos = (size_t)(b * H2 + 2 * t + q) * H2 + jh * 28 + j2;
        __half2 p0 = __floats2half2_rn(ll, lh), p1 = __floats2half2_rn(hl, hh);
        uint2 v; v.x = *(uint32_t*)&p0; v.y = *(uint32_t*)&p1;
        *(uint2*)(a2 + pos * C4 + c * 4) = v;
        ll2s[q][c][j2] = ll;
    }
    __syncthreads();

#pragma unroll
    for (int l = 0; l < 2; l++) {
        int idx = tid + l * 256;
        if (idx < 448) {
            int c3 = idx & 31, j3 = idx >> 5;   // j3 0..13
            float a  = ll2s[0][c3][2 * j3], bb = ll2s[0][c3][2 * j3 + 1];
            float cc = ll2s[1][c3][2 * j3], dd = ll2s[1][c3][2 * j3 + 1];
            float ll = (a + bb + cc + dd) * 0.5f;
            float lh = (a - bb + cc - dd) * 0.5f;
            float hl = (a + bb - cc - dd) * 0.5f;
            float hh = (a - bb - cc + dd) * 0.5f;
            size_t pos = (size_t)(b * H3 + t) * H3 + jh * 14 + j3;
            __half2 p0 = __floats2half2_rn(ll, lh), p1 = __floats2half2_rn(hl, hh);
            uint2 v; v.x = *(uint32_t*)&p0; v.y = *(uint32_t*)&p1;
            *(uint2*)(a3 + pos * C4 + c3 * 4) = v;
        }
    }
}

// ================= fused IDWT cascade (bias + NCHW output) — R13 version =================
__global__ void idwtall_k(const __half* __restrict__ y1, const __half* __restrict__ y2,
                          const __half* __restrict__ y3, float* __restrict__ out,
                          const float* __restrict__ bias) {
    __shared__ float r2s[2][NC][29];
    __shared__ float r1s[4][NC][57];
    __shared__ float outs[2][NC][113];

    int blk = blockIdx.x;
    int jh = blk & 1;
    int t  = (blk >> 1) % 28;
    int b  = (blk >> 1) / 28;
    const int tid = threadIdx.x;
    const int c = tid & 31;
    const float bv = bias[c];

#pragma unroll
    for (int l = 0; l < 2; l++) {
        int idx = tid + l * 256;
        if (idx < 448) {
            int c3 = idx & 31, j3 = idx >> 5;
            size_t pos = (size_t)(b * H3 + t) * H3 + jh * 14 + j3;
            float ll, lh, hl, hh;
            ld_y4(y3 + pos * C4 + c3 * 4, ll, lh, hl, hh);
            float a  = (ll + lh + hl + hh) * 0.5f;
            float bb = (ll - lh + hl - hh) * 0.5f;
            float cc = (ll + lh - hl - hh) * 0.5f;
            float dd = (ll - lh - hl + hh) * 0.5f;
            r2s[0][c3][2 * j3]     = a;
            r2s[0][c3][2 * j3 + 1] = bb;
            r2s[1][c3][2 * j3]     = cc;
            r2s[1][c3][2 * j3 + 1] = dd;
        }
    }
    __syncthreads();

#pragma unroll
    for (int l = 0; l < 7; l++) {
        int idx = (tid >> 5) + l * 8;
        int q = idx / 28, j2 = idx - q * 28;
        size_t pos = (size_t)(b * H2 + 2 * t + q) * H2 + jh * 28 + j2;
        float ll, lh, hl, hh;
        ld_y4(y2 + pos * C4 + c * 4, ll, lh, hl, hh);
        ll += r2s[q][c][j2];
        float a  = (ll + lh + hl + hh) * 0.5f;
        float bb = (ll - lh + hl - hh) * 0.5f;
        float cc = (ll + lh - hl - hh) * 0.5f;
        float dd = (ll - lh - hl + hh) * 0.5f;
        r1s[2 * q][c][2 * j2]         = a;
        r1s[2 * q][c][2 * j2 + 1]     = bb;
        r1s[2 * q + 1][c][2 * j2]     = cc;
        r1s[2 * q + 1][c][2 * j2 + 1] = dd;
    }
    __syncthreads();

    float* ob = out + (size_t)b * NC * 224 * 224 + (size_t)jh * 112;
#pragma unroll 1
    for (int r = 0; r < 4; r++) {
#pragma unroll
        for (int l = 0; l < 7; l++) {
            int jl = (tid >> 5) + l * 8;
            size_t pos = (size_t)(b * H1 + 4 * t + r) * H1 + jh * 56 + jl;
            float ll, lh, hl, hh;
            ld_y4(y1 + pos * C4 + c * 4, ll, lh, hl, hh);
            ll += r1s[r][c][jl];
            float a  = (ll + lh + hl + hh) * 0.5f + bv;
            float bb = (ll - lh + hl - hh) * 0.5f + bv;
            float cc = (ll + lh - hl - hh) * 0.5f + bv;
            float dd = (ll - lh - hl + hh) * 0.5f + bv;
            outs[0][c][2 * jl]     = a;
            outs[0][c][2 * jl + 1] = bb;
            outs[1][c][2 * jl]     = cc;
            outs[1][c][2 * jl + 1] = dd;
        }
        __syncthreads();
#pragma unroll
        for (int it = 0; it < 7; it++) {
            int tt = it * 256 + tid;
            int f4 = tt % 28;
            int c2 = (tt / 28) & 31;
            int rr = tt / (28 * 32);
            const float* sp = &outs[rr][c2][f4 * 4];
            float4 v = make_float4(sp[0], sp[1], sp[2], sp[3]);
            *(float4*)(ob + ((size_t)c2 * 224 + (8 * t + 2 * r + rr)) * 224 + f4 * 4) = v;
        }
        __syncthreads();
    }
}

// ================= conv: halo-A + B double-buffer BK=128, 9 chunks, 8 warps 64x32 =================
__global__ __launch_bounds__(256, 2)
void conv_mma(const __half* __restrict__ a1, __half* __restrict__ y1,
              const __half* __restrict__ a2, __half* __restrict__ y2,
              const __half* __restrict__ a3, __half* __restrict__ y3,
              const __half* __restrict__ wgt) {
    extern __shared__ __align__(128) char smem[];
    const uint32_t haloB = smem_u32(smem);
    const uint32_t bBase = haloB + HALO_BYTES;

    int bid = blockIdx.x;
    const __half* act; __half* y; int h, b, ti, tj;
    if (bid < NT1)            { act = a1; y = y1; h = H1; b = bid / 98; int r = bid % 98; ti = r / 7;  tj = r % 7; }
    else if (bid < NT1 + NT2) { int t = bid - NT1;       act = a2; y = y2; h = H2; b = t / 28; int r = t % 28; ti = r / 4; tj = r % 4; }
    else                      { int t = bid - NT1 - NT2; act = a3; y = y3; h = H3; b = t / 8;  int r = t % 8;  ti = r / 2; tj = r % 2; }
    const int w = h;
    const int oh0 = ti * 8, ow0 = tj * 16;

    const int tid = threadIdx.x;
    const int lane = tid & 31;
    const int wid = tid >> 5;
    const int wm = wid & 1;
    const int wn = wid >> 1;

    // ---- halo load: 10x18 cells x 16 chunks ----
    {
        const size_t actB = (size_t)b * h * w * C4;
#pragma unroll
        for (int it = 0; it < 12; it++) {
            int idx = it * 256 + tid;
            if (idx < 2880) {
                int cell = idx >> 4, q = idx & 15;
                int hr = cell / 18, hc = cell - hr * 18;
                int ih = oh0 + hr - 1, iw = ow0 + hc - 1;
                bool v = ((unsigned)ih < (unsigned)h) && ((unsigned)iw < (unsigned)w);
                const char* src = (const char*)(act + actB + ((size_t)ih * w + iw) * C4 + q * 8);
                uint32_t dst = haloB + (uint32_t)cell * 256 +
                               (uint32_t)((((q & 7) ^ (cell & 7)) + (q & 8)) << 4);
                cp16(dst, src, v ? 16u : 0u);
            }
        }
    }

    // ---- B chunk loader: tap -> 128 n-rows x 128 ic (256B rows), 2048 x 16B ----
    auto load_b = [&](int tap, uint32_t st) {
        const __half* wt = wgt + (size_t)tap * C4 * C4;
#pragma unroll
        for (int it = 0; it < 8; it++) {
            int idx = it * 256 + tid;
            int n = idx >> 4, q = idx & 15;
            const char* src = (const char*)(wt + (size_t)n * C4 + q * 8);
            uint32_t dst = st + (uint32_t)n * 256 +
                           (uint32_t)((((q & 7) ^ (n & 7)) + (q & 8)) << 4);
            cp16(dst, src, 16u);
        }
    };

    // ---- ldmatrix geometry ----
    const int aSeg = lane >> 4;
    const int aJ = lane & 15;
    uint32_t bRowOff[2]; int bSx[2];
#pragma unroll
    for (int bt = 0; bt < 2; bt++) {
        int rowB = wn * 32 + bt * 16 + (lane & 7) + ((lane & 16) >> 1);
        bRowOff[bt] = (uint32_t)rowB * 256;
        bSx[bt] = rowB & 7;
    }
    const int bSeg = (lane >> 3) & 1;

    float acc[4][4][4];
#pragma unroll
    for (int i = 0; i < 4; i++)
#pragma unroll
        for (int j = 0; j < 4; j++)
#pragma unroll
            for (int q = 0; q < 4; q++) acc[i][j][q] = 0.0f;

    load_b(0, bBase);
    CP_COMMIT();                 // g0 = halo + B0

    uint32_t stC = bBase;
    uint32_t stL = bBase + B_STAGE;

#pragma unroll 1
    for (int ch = 0; ch < NCHUNK; ch++) {
        CP_WAIT0();              // chunk ch's B (and halo) landed
        __syncthreads();         // readers of stL's previous contents are done
        if (ch + 1 < NCHUNK) load_b(ch + 1, stL);
        CP_COMMIT();             // prefetch overlaps this chunk's compute

        const int kh = ch / 3;
        const int kw = ch - kh * 3;

        uint32_t aOff[4]; int aC7[4];
#pragma unroll
        for (int mt = 0; mt < 4; mt++) {
            int cell = (wm * 4 + mt + kh) * 18 + kw + aJ;
            aOff[mt] = haloB + (uint32_t)cell * 256;
            aC7[mt] = cell & 7;
        }

#pragma unroll
        for (int ks = 0; ks < 8; ks++) {
            uint32_t af[4][4];
            const int qa = ks * 2 + aSeg;
#pragma unroll
            for (int mt = 0; mt < 4; mt++) {
                uint32_t addr = aOff[mt] +
                    (uint32_t)((((qa & 7) ^ aC7[mt]) + (qa & 8)) << 4);
                ldsm_x4(af[mt][0], af[mt][1], af[mt][2], af[mt][3], addr);
            }
            uint32_t bf[4][2];
            const int qb = ks * 2 + bSeg;
#pragma unroll
            for (int bt = 0; bt < 2; bt++) {
                uint32_t r0, r1, r2, r3;
                uint32_t addr = stC + bRowOff[bt] +
                    (uint32_t)((((qb & 7) ^ bSx[bt]) + (qb & 8)) << 4);
                ldsm_x4(r0, r1, r2, r3, addr);
                bf[bt * 2 + 0][0] = r0; bf[bt * 2 + 0][1] = r1;
                bf[bt * 2 + 1][0] = r2; bf[bt * 2 + 1][1] = r3;
            }
#pragma unroll
            for (int mt = 0; mt < 4; mt++)
#pragma unroll
                for (int nt = 0; nt < 4; nt++)
                    mma16816(acc[mt][nt], af[mt], bf[nt]);
        }

        uint32_t tmp = stC; stC = stL; stL = tmp;
    }

    // ---- epilogue: fp16 stores ----
    const int jc = lane >> 2;
    const int nBase = wn * 32 + (lane & 3) * 2;
#pragma unroll
    for (int mt = 0; mt < 4; mt++) {
        int oh = oh0 + wm * 4 + mt;
        int ow = ow0 + jc;
        bool ohv = oh < h;
        bool v0 = ohv && (ow < w);
        bool v1 = ohv && (ow + 8 < w);
        __half* d0 = y + ((size_t)(b * h + oh) * w + ow) * C4 + nBase;
        __half* d1 = d0 + 8 * C4;
#pragma unroll
        for (int nt = 0; nt < 4; nt++) {
            if (v0) *(__half2*)(d0 + nt * 8) = __floats2half2_rn(acc[mt][nt][0], acc[mt][nt][1]);
            if (v1) *(__half2*)(d1 + nt * 8) = __floats2half2_rn(acc[mt][nt][2], acc[mt][nt][3]);
        }
    }
}

// ================= launch =================
extern "C" void kernel_launch(void* const* d_in, const int* in_sizes, int n_in,
                              void* d_out, int out_size) {
    const float* x    = (const float*)d_in[0];
    const float* wgt  = (const float*)d_in[1];
    const float* bias = (const float*)d_in[2];
    float* out = (float*)d_out;

    __half *a1, *a2, *a3, *wh, *y1, *y2, *y3;
    cudaGetSymbolAddress((void**)&a1, g_a1);
    cudaGetSymbolAddress((void**)&a2, g_a2);
    cudaGetSymbolAddress((void**)&a3, g_a3);
    cudaGetSymbolAddress((void**)&wh, g_w);
    cudaGetSymbolAddress((void**)&y1, g_y1);
    cudaGetSymbolAddress((void**)&y2, g_y2);
    cudaGetSymbolAddress((void**)&y3, g_y3);

    cudaFuncSetAttribute(conv_mma, cudaFuncAttributeMaxDynamicSharedMemorySize, SMEM_TOTAL);

    // 0: full DWT cascade + weight convert
    dwtall_k<<<WCONV_BLKS + CASC_BLKS, 256>>>(x, wgt, wh, a1, a2, a3);
    // 1: all convs
    conv_mma<<<NT1 + NT2 + NT3, 256, SMEM_TOTAL>>>(a1, y1, a2, y2, a3, y3, wh);
    // 2: full IDWT cascade + bias + NCHW output
    idwtall_k<<<CASC_BLKS, 256>>>(y1, y2, y3, out, bias);
}

// round 17
// speedup vs baseline: 1.1373x; 1.0482x over previous
#include <cuda_runtime.h>
#include <cuda_fp16.h>
#include <cstdint>
#include <cstddef>

// ================= problem constants =================
#define NB 8
#define NC 32
#define C4 128
#define H1 112
#define H2 56
#define H3 28
#define M1 (NB * H1 * H1)
#define M2 (NB * H2 * H2)
#define M3 (NB * H3 * H3)

// conv spatial tile: 8 x 16 = 128 M-rows per block
#define NT1 (NB * 14 * 7)   // 784
#define NT2 (NB * 7 * 4)    // 224
#define NT3 (NB * 4 * 2)    // 64

#define NCHUNK 9            // 9 taps, BK=128
#define HALO_BYTES 46080    // 10*18 cells * 256B
#define SMEM_TOTAL HALO_BYTES

#define WFRAG_ENTRIES (9 * 8 * 8 * 32)      // (tap, n16 g, ks, lane) -> 16B payload
#define WCONV_BLKS (WFRAG_ENTRIES / 256)    // 72
#define CASC_BLKS (NB * 28 * 2)             // 448

// ================= scratch =================
__device__ __half g_a1[(size_t)M1 * C4];
__device__ __half g_a2[(size_t)M2 * C4];
__device__ __half g_a3[(size_t)M3 * C4];
__device__ __half g_y1 [(size_t)M1 * C4];
__device__ __half g_y2 [(size_t)M2 * C4];
__device__ __half g_y3 [(size_t)M3 * C4];
__device__ __half g_wf[(size_t)WFRAG_ENTRIES * 8];   // fragment-layout weights

// ================= helpers =================
__device__ __forceinline__ uint32_t smem_u32(const void* p) {
    uint32_t a;
    asm("{ .reg .u64 t; cvta.to.shared.u64 t, %1; cvt.u32.u64 %0, t; }" : "=r"(a) : "l"(p));
    return a;
}
__device__ __forceinline__ void ldsm_x4(uint32_t& r0, uint32_t& r1, uint32_t& r2, uint32_t& r3,
                                        uint32_t addr) {
    asm volatile("ldmatrix.sync.aligned.m8n8.x4.shared.b16 {%0,%1,%2,%3}, [%4];"
                 : "=r"(r0), "=r"(r1), "=r"(r2), "=r"(r3) : "r"(addr));
}
__device__ __forceinline__ void mma16816(float* c, const uint32_t* a, const uint32_t* b) {
    asm volatile(
        "mma.sync.aligned.m16n8k16.row.col.f32.f16.f16.f32 "
        "{%0,%1,%2,%3}, {%4,%5,%6,%7}, {%8,%9}, {%0,%1,%2,%3};"
        : "+f"(c[0]), "+f"(c[1]), "+f"(c[2]), "+f"(c[3])
        : "r"(a[0]), "r"(a[1]), "r"(a[2]), "r"(a[3]), "r"(b[0]), "r"(b[1]));
}
__device__ __forceinline__ void cp16(uint32_t saddr, const void* gptr, uint32_t srcsz) {
    size_t ga = __cvta_generic_to_global(gptr);
    asm volatile("cp.async.cg.shared.global [%0], [%1], 16, %2;"
                 :: "r"(saddr), "l"(ga), "r"(srcsz) : "memory");
}
#define CP_COMMIT()  asm volatile("cp.async.commit_group;" ::: "memory")
#define CP_WAIT0()   asm volatile("cp.async.wait_group 0;" ::: "memory")

__device__ __forceinline__ void ld_y4(const __half* p, float& v0, float& v1, float& v2, float& v3) {
    uint2 raw = *(const uint2*)p;
    __half2 h0 = *(__half2*)&raw.x;
    __half2 h1 = *(__half2*)&raw.y;
    v0 = __low2float(h0); v1 = __high2float(h0);
    v2 = __low2float(h1); v3 = __high2float(h1);
}

// ================= fused DWT cascade (+ weight-fragment blocks) =================
__global__ void dwtall_k(const float* __restrict__ x, const float* __restrict__ w,
                         __half* __restrict__ wf, __half* __restrict__ a1,
                         __half* __restrict__ a2, __half* __restrict__ a3) {
    if (blockIdx.x < WCONV_BLKS) {
        // fragment layout: e = ((tap*8+g)*8+ks)*32+lane ; payload 8 halfs
        int e = blockIdx.x * 256 + threadIdx.x;
        int lane = e & 31;
        int ks   = (e >> 5) & 7;
        int g    = (e >> 8) & 7;
        int tap  = e >> 11;
        int n0 = g * 16 + (lane >> 2);
        int k0 = ks * 16 + (lane & 3) * 2;
        // B[n][k] = w[(n*C4 + k)*9 + tap]
        const float* wb = w + tap;
        float h0 = wb[((size_t)n0 * C4 + k0) * 9];
        float h1 = wb[((size_t)n0 * C4 + k0 + 1) * 9];
        float h2 = wb[((size_t)n0 * C4 + k0 + 8) * 9];
        float h3 = wb[((size_t)n0 * C4 + k0 + 9) * 9];
        float h4 = wb[((size_t)(n0 + 8) * C4 + k0) * 9];
        float h5 = wb[((size_t)(n0 + 8) * C4 + k0 + 1) * 9];
        float h6 = wb[((size_t)(n0 + 8) * C4 + k0 + 8) * 9];
        float h7 = wb[((size_t)(n0 + 8) * C4 + k0 + 9) * 9];
        __half2 p0 = __floats2half2_rn(h0, h1);
        __half2 p1 = __floats2half2_rn(h2, h3);
        __half2 p2 = __floats2half2_rn(h4, h5);
        __half2 p3 = __floats2half2_rn(h6, h7);
        uint4 v;
        v.x = *(uint32_t*)&p0; v.y = *(uint32_t*)&p1;
        v.z = *(uint32_t*)&p2; v.w = *(uint32_t*)&p3;
        *(uint4*)(wf + (size_t)e * 8) = v;
        return;
    }
    __shared__ float xrow[2][NC][113];
    __shared__ float ll1s[4][NC][57];
    __shared__ float ll2s[2][NC][29];

    int blk = blockIdx.x - WCONV_BLKS;
    int jh = blk & 1;
    int t  = (blk >> 1) % 28;
    int b  = (blk >> 1) / 28;
    const int tid = threadIdx.x;
    const int c = tid & 31;
    const float* xb = x + (size_t)b * NC * 224 * 224 + (size_t)jh * 112;

#pragma unroll 1
    for (int r = 0; r < 4; r++) {
#pragma unroll
        for (int it = 0; it < 7; it++) {
            int tt = it * 256 + tid;
            int f4 = tt % 28;
            int cc = (tt / 28) & 31;
            int rr = tt / (28 * 32);
            float4 v = *(const float4*)(xb + ((size_t)cc * 224 + (8 * t + 2 * r + rr)) * 224 + f4 * 4);
            float* d = &xrow[rr][cc][f4 * 4];
            d[0] = v.x; d[1] = v.y; d[2] = v.z; d[3] = v.w;
        }
        __syncthreads();
#pragma unroll
        for (int l = 0; l < 7; l++) {
            int jl = (tid >> 5) + l * 8;    // 0..55
            float a  = xrow[0][c][2 * jl],  bb = xrow[0][c][2 * jl + 1];
            float cc = xrow[1][c][2 * jl],  dd = xrow[1][c][2 * jl + 1];
            float ll = (a + bb + cc + dd) * 0.5f;
            float lh = (a - bb + cc - dd) * 0.5f;
            float hl = (a + bb - cc - dd) * 0.5f;
            float hh = (a - bb - cc + dd) * 0.5f;
            size_t pos = (size_t)(b * H1 + 4 * t + r) * H1 + jh * 56 + jl;
            __half2 p0 = __floats2half2_rn(ll, lh), p1 = __floats2half2_rn(hl, hh);
            uint2 v; v.x = *(uint32_t*)&p0; v.y = *(uint32_t*)&p1;
            *(uint2*)(a1 + pos * C4 + c * 4) = v;
            ll1s[r][c][jl] = ll;
        }
        __syncthreads();
    }

#pragma unroll
    for (int l = 0; l < 7; l++) {
        int idx = (tid >> 5) + l * 8;       // 0..55
        int q = idx / 28, j2 = idx - q * 28;
        float a  = ll1s[2 * q][c][2 * j2],     bb = ll1s[2 * q][c][2 * j2 + 1];
        float cc = ll1s[2 * q + 1][c][2 * j2], dd = ll1s[2 * q + 1][c][2 * j2 + 1];
        float ll = (a + bb + cc + dd) * 0.5f;
        float lh = (a - bb + cc - dd) * 0.5f;
        float hl = (a + bb - cc - dd) * 0.5f;
        float hh = (a - bb - cc + dd) * 0.5f;
        size_t pos = (size_t)(b * H2 + 2 * t + q) * H2 + jh * 28 + j2;
        __half2 p0 = __floats2half2_rn(ll, lh), p1 = __floats2half2_rn(hl, hh);
        uint2 v; v.x = *(uint32_t*)&p0; v.y = *(uint32_t*)&p1;
        *(uint2*)(a2 + pos * C4 + c * 4) = v;
        ll2s[q][c][j2] = ll;
    }
    __syncthreads();

#pragma unroll
    for (int l = 0; l < 2; l++) {
        int idx = tid + l * 256;
        if (idx < 448) {
            int c3 = idx & 31, j3 = idx >> 5;   // j3 0..13
            float a  = ll2s[0][c3][2 * j3], bb = ll2s[0][c3][2 * j3 + 1];
            float cc = ll2s[1][c3][2 * j3], dd = ll2s[1][c3][2 * j3 + 1];
            float ll = (a + bb + cc + dd) * 0.5f;
            float lh = (a - bb + cc - dd) * 0.5f;
            float hl = (a + bb - cc - dd) * 0.5f;
            float hh = (a - bb - cc + dd) * 0.5f;
            size_t pos = (size_t)(b * H3 + t) * H3 + jh * 14 + j3;
            __half2 p0 = __floats2half2_rn(ll, lh), p1 = __floats2half2_rn(hl, hh);
            uint2 v; v.x = *(uint32_t*)&p0; v.y = *(uint32_t*)&p1;
            *(uint2*)(a3 + pos * C4 + c3 * 4) = v;
        }
    }
}

// ================= fused IDWT cascade (bias + NCHW output) =================
__global__ void idwtall_k(const __half* __restrict__ y1, const __half* __restrict__ y2,
                          const __half* __restrict__ y3, float* __restrict__ out,
                          const float* __restrict__ bias) {
    __shared__ float r2s[2][NC][29];
    __shared__ float r1s[4][NC][57];
    __shared__ float outs[2][NC][113];

    int blk = blockIdx.x;
    int jh = blk & 1;
    int t  = (blk >> 1) % 28;
    int b  = (blk >> 1) / 28;
    const int tid = threadIdx.x;
    const int c = tid & 31;
    const float bv = bias[c];

#pragma unroll
    for (int l = 0; l < 2; l++) {
        int idx = tid + l * 256;
        if (idx < 448) {
            int c3 = idx & 31, j3 = idx >> 5;
            size_t pos = (size_t)(b * H3 + t) * H3 + jh * 14 + j3;
            float ll, lh, hl, hh;
            ld_y4(y3 + pos * C4 + c3 * 4, ll, lh, hl, hh);
            float a  = (ll + lh + hl + hh) * 0.5f;
            float bb = (ll - lh + hl - hh) * 0.5f;
            float cc = (ll + lh - hl - hh) * 0.5f;
            float dd = (ll - lh - hl + hh) * 0.5f;
            r2s[0][c3][2 * j3]     = a;
            r2s[0][c3][2 * j3 + 1] = bb;
            r2s[1][c3][2 * j3]     = cc;
            r2s[1][c3][2 * j3 + 1] = dd;
        }
    }
    __syncthreads();

#pragma unroll
    for (int l = 0; l < 7; l++) {
        int idx = (tid >> 5) + l * 8;
        int q = idx / 28, j2 = idx - q * 28;
        size_t pos = (size_t)(b * H2 + 2 * t + q) * H2 + jh * 28 + j2;
        float ll, lh, hl, hh;
        ld_y4(y2 + pos * C4 + c * 4, ll, lh, hl, hh);
        ll += r2s[q][c][j2];
        float a  = (ll + lh + hl + hh) * 0.5f;
        float bb = (ll - lh + hl - hh) * 0.5f;
        float cc = (ll + lh - hl - hh) * 0.5f;
        float dd = (ll - lh - hl + hh) * 0.5f;
        r1s[2 * q][c][2 * j2]         = a;
        r1s[2 * q][c][2 * j2 + 1]     = bb;
        r1s[2 * q + 1][c][2 * j2]     = cc;
        r1s[2 * q + 1][c][2 * j2 + 1] = dd;
    }
    __syncthreads();

    float* ob = out + (size_t)b * NC * 224 * 224 + (size_t)jh * 112;
#pragma unroll 1
    for (int r = 0; r < 4; r++) {
#pragma unroll
        for (int l = 0; l < 7; l++) {
            int jl = (tid >> 5) + l * 8;
            size_t pos = (size_t)(b * H1 + 4 * t + r) * H1 + jh * 56 + jl;
            float ll, lh, hl, hh;
            ld_y4(y1 + pos * C4 + c * 4, ll, lh, hl, hh);
            ll += r1s[r][c][jl];
            float a  = (ll + lh + hl + hh) * 0.5f + bv;
            float bb = (ll - lh + hl - hh) * 0.5f + bv;
            float cc = (ll + lh - hl - hh) * 0.5f + bv;
            float dd = (ll - lh - hl + hh) * 0.5f + bv;
            outs[0][c][2 * jl]     = a;
            outs[0][c][2 * jl + 1] = bb;
            outs[1][c][2 * jl]     = cc;
            outs[1][c][2 * jl + 1] = dd;
        }
        __syncthreads();
#pragma unroll
        for (int it = 0; it < 7; it++) {
            int tt = it * 256 + tid;
            int f4 = tt % 28;
            int c2 = (tt / 28) & 31;
            int rr = tt / (28 * 32);
            const float* sp = &outs[rr][c2][f4 * 4];
            float4 v = make_float4(sp[0], sp[1], sp[2], sp[3]);
            *(float4*)(ob + ((size_t)c2 * 224 + (8 * t + 2 * r + rr)) * 224 + f4 * 4) = v;
        }
        __syncthreads();
    }
}

// ================= conv: halo-A smem + B fragments via LDG; barrier-free mainloop =================
__global__ __launch_bounds__(256, 2)
void conv_mma(const __half* __restrict__ a1, __half* __restrict__ y1,
              const __half* __restrict__ a2, __half* __restrict__ y2,
              const __half* __restrict__ a3, __half* __restrict__ y3,
              const __half* __restrict__ wf) {
    extern __shared__ __align__(128) char smem[];
    const uint32_t haloB = smem_u32(smem);

    int bid = blockIdx.x;
    const __half* act; __half* y; int h, b, ti, tj;
    if (bid < NT1)            { act = a1; y = y1; h = H1; b = bid / 98; int r = bid % 98; ti = r / 7;  tj = r % 7; }
    else if (bid < NT1 + NT2) { int t = bid - NT1;       act = a2; y = y2; h = H2; b = t / 28; int r = t % 28; ti = r / 4; tj = r % 4; }
    else                      { int t = bid - NT1 - NT2; act = a3; y = y3; h = H3; b = t / 8;  int r = t % 8;  ti = r / 2; tj = r % 2; }
    const int w = h;
    const int oh0 = ti * 8, ow0 = tj * 16;

    const int tid = threadIdx.x;
    const int lane = tid & 31;
    const int wid = tid >> 5;
    const int wm = wid & 1;
    const int wn = wid >> 1;

    // ---- halo load: 10x18 cells x 16 chunks ----
    {
        const size_t actB = (size_t)b * h * w * C4;
#pragma unroll
        for (int it = 0; it < 12; it++) {
            int idx = it * 256 + tid;
            if (idx < 2880) {
                int cell = idx >> 4, q = idx & 15;
                int hr = cell / 18, hc = cell - hr * 18;
                int ih = oh0 + hr - 1, iw = ow0 + hc - 1;
                bool v = ((unsigned)ih < (unsigned)h) && ((unsigned)iw < (unsigned)w);
                const char* src = (const char*)(act + actB + ((size_t)ih * w + iw) * C4 + q * 8);
                uint32_t dst = haloB + (uint32_t)cell * 256 +
                               (uint32_t)((((q & 7) ^ (cell & 7)) + (q & 8)) << 4);
                cp16(dst, src, v ? 16u : 0u);
            }
        }
    }
    CP_COMMIT();

    // ---- B fragment base for this warp: e = ((tap*8 + wn*2+bt)*8 + ks)*32 + lane ----
    const uint4* wfb = (const uint4*)wf + (size_t)(wn * 2) * 8 * 32 + lane;
    // per tap add tap*8*8*32 = tap*2048 ; per bt add 8*32=256 ; per ks add 32

    // ---- ldmatrix A geometry ----
    const int aSeg = lane >> 4;
    const int aJ = lane & 15;

    float acc[4][4][4];
#pragma unroll
    for (int i = 0; i < 4; i++)
#pragma unroll
        for (int j = 0; j < 4; j++)
#pragma unroll
            for (int q = 0; q < 4; q++) acc[i][j][q] = 0.0f;

    CP_WAIT0();
    __syncthreads();     // halo visible to all warps; no further barriers

#pragma unroll 1
    for (int ch = 0; ch < NCHUNK; ch++) {
        const int kh = ch / 3;
        const int kw = ch - kh * 3;
        const uint4* wft = wfb + (size_t)ch * 2048;

        uint32_t aOff[4]; int aC7[4];
#pragma unroll
        for (int mt = 0; mt < 4; mt++) {
            int cell = (wm * 4 + mt + kh) * 18 + kw + aJ;
            aOff[mt] = haloB + (uint32_t)cell * 256;
            aC7[mt] = cell & 7;
        }

#pragma unroll
        for (int ks = 0; ks < 8; ks++) {
            uint32_t bf[4][2];
#pragma unroll
            for (int bt = 0; bt < 2; bt++) {
                uint4 v = __ldg(wft + bt * 256 + ks * 32);
                bf[bt * 2 + 0][0] = v.x; bf[bt * 2 + 0][1] = v.y;
                bf[bt * 2 + 1][0] = v.z; bf[bt * 2 + 1][1] = v.w;
            }
            uint32_t af[4][4];
            const int qa = ks * 2 + aSeg;
#pragma unroll
            for (int mt = 0; mt < 4; mt++) {
                uint32_t addr = aOff[mt] +
                    (uint32_t)((((qa & 7) ^ aC7[mt]) + (qa & 8)) << 4);
                ldsm_x4(af[mt][0], af[mt][1], af[mt][2], af[mt][3], addr);
            }
#pragma unroll
            for (int mt = 0; mt < 4; mt++)
#pragma unroll
                for (int nt = 0; nt < 4; nt++)
                    mma16816(acc[mt][nt], af[mt], bf[nt]);
        }
    }

    // ---- epilogue: fp16 stores ----
    const int jc = lane >> 2;
    const int nBase = wn * 32 + (lane & 3) * 2;
#pragma unroll
    for (int mt = 0; mt < 4; mt++) {
        int oh = oh0 + wm * 4 + mt;
        int ow = ow0 + jc;
        bool ohv = oh < h;
        bool v0 = ohv && (ow < w);
        bool v1 = ohv && (ow + 8 < w);
        __half* d0 = y + ((size_t)(b * h + oh) * w + ow) * C4 + nBase;
        __half* d1 = d0 + 8 * C4;
#pragma unroll
        for (int nt = 0; nt < 4; nt++) {
            if (v0) *(__half2*)(d0 + nt * 8) = __floats2half2_rn(acc[mt][nt][0], acc[mt][nt][1]);
            if (v1) *(__half2*)(d1 + nt * 8) = __floats2half2_rn(acc[mt][nt][2], acc[mt][nt][3]);
        }
    }
}

// ================= launch =================
extern "C" void kernel_launch(void* const* d_in, const int* in_sizes, int n_in,
                              void* d_out, int out_size) {
    const float* x    = (const float*)d_in[0];
    const float* wgt  = (const float*)d_in[1];
    const float* bias = (const float*)d_in[2];
    float* out = (float*)d_out;

    __half *a1, *a2, *a3, *wfp, *y1, *y2, *y3;
    cudaGetSymbolAddress((void**)&a1, g_a1);
    cudaGetSymbolAddress((void**)&a2, g_a2);
    cudaGetSymbolAddress((void**)&a3, g_a3);
    cudaGetSymbolAddress((void**)&wfp, g_wf);
    cudaGetSymbolAddress((void**)&y1, g_y1);
    cudaGetSymbolAddress((void**)&y2, g_y2);
    cudaGetSymbolAddress((void**)&y3, g_y3);

    cudaFuncSetAttribute(conv_mma, cudaFuncAttributeMaxDynamicSharedMemorySize, SMEM_TOTAL);

    // 0: full DWT cascade + weight fragment layout
    dwtall_k<<<WCONV_BLKS + CASC_BLKS, 256>>>(x, wgt, wfp, a1, a2, a3);
    // 1: all convs (barrier-free mainloop)
    conv_mma<<<NT1 + NT2 + NT3, 256, SMEM_TOTAL>>>(a1, y1, a2, y2, a3, y3, wfp);
    // 2: full IDWT cascade + bias + NCHW output
    idwtall_k<<<CASC_BLKS, 256>>>(y1, y2, y3, out, bias);
}